// round 11
// baseline (speedup 1.0000x reference)
#include <cuda_runtime.h>
#include <cstdint>
#include <cstddef>

// ---------------------------------------------------------------------------
// Covariance:  cov[b] = (X^T X)/N - mu mu^T, packed upper triangle.
// X: [64, 4096, 256] f32 -> out: [64, 32896] f32
// TF32 mma.sync m16n8k8 SYRK, triangle-only (80 n-units of 64m x 8n / batch,
// 16 warp-slots x 5 units). 2 CTAs/batch, 256 thr (8 warps, 2/SMSP).
// KEY CHANGE vs R7/R8/R9: register-fragment DOUBLE BUFFERING — k-step ks+1's
// smem fragments are loaded while ks's MMAs occupy the tensor pipe, removing
// the LDS->HMMA latency from the critical path (the serialization all prior
// rounds measured). KC=32, staging in two v[4] sub-batches (16 live regs).
// ---------------------------------------------------------------------------

static constexpr int BATCH  = 64;
static constexpr int NPTS   = 4096;
static constexpr int DIM    = 256;
static constexpr int TRI    = DIM * (DIM + 1) / 2;   // 32896
static constexpr int KC     = 32;
static constexpr int NCHUNK = NPTS / KC;             // 128
static constexpr int SROW   = 264;                   // 264 % 32 == 8 -> conflict-free
static constexpr int STAGE_F = KC * SROW;            // 8448 floats
static constexpr int SMEM_FLOATS = 2 * STAGE_F + 4 * 256 + 256;
static constexpr int SMEM_BYTES  = SMEM_FLOATS * 4;  // 72704

// slot tables (verified in R8): slot -> (mA, nA0, cntA, mB, nB0).
__device__ const int8_t SLOT_MA[16] = {0,0,0,0,0,0,0,1, 1,1,1,1,2,2,2,3};
__device__ const int8_t SLOT_NA[16] = {0,5,10,15,20,25,30,11, 16,21,26,31,20,25,30,27};
__device__ const int8_t SLOT_CA[16] = {5,5,5,5,5,5,2,5, 5,5,5,1,5,5,2,5};
__device__ const int8_t SLOT_MB[16] = {0,0,0,0,0,0,1,0, 0,0,0,2,0,0,3,0};
__device__ const int8_t SLOT_NB[16] = {0,0,0,0,0,0,8,0, 0,0,0,16,0,0,24,0};
// boundary slots (6,14,11) on distinct SMSPs.
__device__ const int8_t SLOT_OF[2][8] = {
    {0, 6, 2, 4, 8, 10, 12, 14},
    {1, 3, 5, 7, 9, 11, 13, 15}};

#define MMA_TF32(ac, A, b0, b1)                                                 \
    asm volatile(                                                               \
        "mma.sync.aligned.m16n8k8.row.col.f32.tf32.tf32.f32 "                   \
        "{%0,%1,%2,%3}, {%4,%5,%6,%7}, {%8,%9}, {%0,%1,%2,%3};"                 \
        : "+f"((ac)[0]), "+f"((ac)[1]), "+f"((ac)[2]), "+f"((ac)[3])            \
        : "r"((A)[0]), "r"((A)[1]), "r"((A)[2]), "r"((A)[3]),                   \
          "r"(b0), "r"(b1))

static __device__ __forceinline__ uint32_t cvt_rna_tf32(float v) {
    uint32_t r;
    asm("cvt.rna.tf32.f32 %0, %1;" : "=r"(r) : "f"(v));
    return r;
}

// one k-step's register fragments: slab-A A-frags + all 5 B-frags.
struct KF {
    uint32_t afA[4][4];
    uint32_t bf[5][2];
};

static __device__ __forceinline__ void load_kf(
    const uint32_t* __restrict__ cur, int k8, int mA64,
    const int (&nb8)[5], KF& f, int g, int tig)
{
    const uint32_t* r0p = cur + (k8 + tig) * SROW;
    const uint32_t* r1p = cur + (k8 + tig + 4) * SROW;
#pragma unroll
    for (int mf = 0; mf < 4; ++mf) {
        const int m0 = mA64 + mf * 16 + g;
        f.afA[mf][0] = r0p[m0];
        f.afA[mf][1] = r0p[m0 + 8];
        f.afA[mf][2] = r1p[m0];
        f.afA[mf][3] = r1p[m0 + 8];
    }
#pragma unroll
    for (int u = 0; u < 5; ++u) {
        f.bf[u][0] = r0p[nb8[u] + g];
        f.bf[u][1] = r1p[nb8[u] + g];
    }
}

static __device__ __forceinline__ void mma_kf(
    const uint32_t* __restrict__ cur, int k8, const KF& f,
    int cA, int mB64, float (&acc)[5][4][4], int g, int tig)
{
    // slab-A units: operands were prefetched one k-step ago -> no stall.
#pragma unroll
    for (int u = 0; u < 5; ++u) {
        if (u < cA) {
#pragma unroll
            for (int mf = 0; mf < 4; ++mf)
                MMA_TF32(acc[u][mf], f.afA[mf], f.bf[u][0], f.bf[u][1]);
        }
    }
    if (cA < 5) {   // 3 of 16 warp-slots straddle a slab boundary
        const uint32_t* r0p = cur + (k8 + tig) * SROW;
        const uint32_t* r1p = cur + (k8 + tig + 4) * SROW;
        uint32_t afB[4][4];
#pragma unroll
        for (int mf = 0; mf < 4; ++mf) {
            const int m0 = mB64 + mf * 16 + g;
            afB[mf][0] = r0p[m0];
            afB[mf][1] = r0p[m0 + 8];
            afB[mf][2] = r1p[m0];
            afB[mf][3] = r1p[m0 + 8];
        }
#pragma unroll
        for (int u = 0; u < 5; ++u) {
            if (u >= cA) {
#pragma unroll
                for (int mf = 0; mf < 4; ++mf)
                    MMA_TF32(acc[u][mf], afB[mf], f.bf[u][0], f.bf[u][1]);
            }
        }
    }
}

__global__ void __launch_bounds__(256, 1)
cov_mma_kernel(const float* __restrict__ X, float* __restrict__ out)
{
    extern __shared__ float sm[];
    float* buf0 = sm;
    float* buf1 = sm + STAGE_F;
    float* psum = sm + 2 * STAGE_F;        // [4][256]
    float* csum = psum + 4 * 256;          // [256]

    const int tid  = threadIdx.x;
    const int lane = tid & 31;
    const int wid  = tid >> 5;
    const int b    = blockIdx.x >> 1;
    const int h    = blockIdx.x & 1;
    const int g    = lane >> 2;
    const int tig  = lane & 3;

    // ---- unit assignment ----
    const int slot = SLOT_OF[h][wid];
    const int mA64 = (int)SLOT_MA[slot] * 64;
    const int cA   = (int)SLOT_CA[slot];
    const int mB64 = (int)SLOT_MB[slot] * 64;
    int nb8[5];
    {
        const int nA = SLOT_NA[slot], nB = SLOT_NB[slot];
#pragma unroll
        for (int u = 0; u < 5; ++u)
            nb8[u] = ((u < cA) ? (nA + u) : (nB + (u - cA))) * 8;
    }

    // staging: thread t owns float4 lane t + 256j; rows (t>>6) + 4j
    const float4* gp =
        reinterpret_cast<const float4*>(X + (size_t)b * NPTS * DIM) + tid;
    const int dq    = (tid & 63) * 4;
    const int krow0 = tid >> 6;            // 0..3

    float acc[5][4][4] = {};
    float s4[4] = {0.f, 0.f, 0.f, 0.f};
    float4 v[4];

#define STAGE_GROUP(dst, j) do {                                                \
        uint32_t r0 = cvt_rna_tf32(v[(j) & 3].x), r1 = cvt_rna_tf32(v[(j) & 3].y); \
        uint32_t r2 = cvt_rna_tf32(v[(j) & 3].z), r3 = cvt_rna_tf32(v[(j) & 3].w); \
        s4[0] += __uint_as_float(r0); s4[1] += __uint_as_float(r1);             \
        s4[2] += __uint_as_float(r2); s4[3] += __uint_as_float(r3);             \
        *reinterpret_cast<float4*>(&(dst)[(krow0 + 4 * (j)) * SROW + dq]) =     \
            make_float4(__uint_as_float(r0), __uint_as_float(r1),               \
                        __uint_as_float(r2), __uint_as_float(r3));              \
    } while (0)

    // ---- prologue: stage chunk 0 ----
#pragma unroll
    for (int half = 0; half < 2; ++half) {
#pragma unroll
        for (int j = 0; j < 4; ++j) v[j] = gp[(half * 4 + j) * 256];
#pragma unroll
        for (int j = 0; j < 4; ++j) STAGE_GROUP(buf0, half * 4 + j);
    }
    __syncthreads();

#pragma unroll 1
    for (int c = 0; c < NCHUNK; ++c) {
        const bool more = (c + 1 < NCHUNK);
        const uint32_t* cur =
            reinterpret_cast<const uint32_t*>((c & 1) ? buf1 : buf0);
        float* nxt = (c & 1) ? buf0 : buf1;

        if (more) {                     // LDG batch A for chunk c+1
#pragma unroll
            for (int j = 0; j < 4; ++j)
                v[j] = gp[(c + 1) * 2048 + j * 256];
        }

        KF F[2];
        load_kf(cur, 0, mA64, nb8, F[0], g, tig);
#pragma unroll
        for (int ks = 0; ks < 4; ++ks) {
            if (ks < 3)
                load_kf(cur, (ks + 1) * 8, mA64, nb8, F[(ks + 1) & 1], g, tig);
            mma_kf(cur, ks * 8, F[ks & 1], cA, mB64, acc, g, tig);
            if (ks == 1 && more) {
#pragma unroll
                for (int j = 0; j < 4; ++j) STAGE_GROUP(nxt, j);
#pragma unroll
                for (int j = 0; j < 4; ++j)   // LDG batch B
                    v[j] = gp[(c + 1) * 2048 + (4 + j) * 256];
            }
        }

        if (more) {
#pragma unroll
            for (int j = 0; j < 4; ++j) STAGE_GROUP(nxt, 4 + j);
        }
        __syncthreads();
    }

    // ---- column-sum reduction ----
    psum[krow0 * 256 + dq + 0] = s4[0];
    psum[krow0 * 256 + dq + 1] = s4[1];
    psum[krow0 * 256 + dq + 2] = s4[2];
    psum[krow0 * 256 + dq + 3] = s4[3];
    __syncthreads();
    csum[tid] = psum[tid] + psum[256 + tid] + psum[512 + tid] + psum[768 + tid];
    __syncthreads();

    // ---- epilogue: cov = acc/N - mu_d mu_e, packed upper triangle ----
    const float invN = 1.0f / (float)NPTS;
    const size_t outb = (size_t)b * TRI;

#pragma unroll
    for (int u = 0; u < 5; ++u) {
        const int mb = (u < cA) ? mA64 : mB64;
#pragma unroll
        for (int mf = 0; mf < 4; ++mf) {
#pragma unroll
            for (int cc = 0; cc < 4; ++cc) {
                const int d = mb + mf * 16 + g + (cc >> 1) * 8;
                const int e = nb8[u] + 2 * tig + (cc & 1);
                if (e >= d) {
                    const float mu_d = csum[d] * invN;
                    const float mu_e = csum[e] * invN;
                    const int idx = d * DIM - (d * (d - 1)) / 2 - d + e;
                    out[outb + (size_t)idx] = acc[u][mf][cc] * invN - mu_d * mu_e;
                }
            }
        }
    }
}

extern "C" void kernel_launch(void* const* d_in, const int* in_sizes, int n_in,
                              void* d_out, int out_size)
{
    const float* X = (const float*)d_in[0];
    float* out = (float*)d_out;
    cudaFuncSetAttribute(cov_mma_kernel,
                         cudaFuncAttributeMaxDynamicSharedMemorySize,
                         SMEM_BYTES);
    cov_mma_kernel<<<BATCH * 2, 256, SMEM_BYTES>>>(X, out);
}